// round 4
// baseline (speedup 1.0000x reference)
#include <cuda_runtime.h>
#include <cstdint>

// out[b, p*20+x, q*20+y] = (x!=y && p!=q) ? P[x,p]+Q[x,q]+Q[y,p]+P[y,q] : 0
//                          + (p==q && x==y) ? Mn[x,p] : 0
// P = F1 @ relu(L1) @ F2^T, Q = F1 @ relu(L2) @ F2^T, Mn = U1 @ U2^T (per batch)

#define NB 256
#define NN 20
#define DD 256
#define STRD 260       // row stride (floats) for [20][256] smem tiles
#define CHUNK 16       // weight rows staged per smem tile

typedef unsigned long long ull;

__device__ float g_scratch[NB * 1200];   // per batch: P[400] | Q[400] | Mn[400]

#define FMA2(acc, x, y) \
    asm("fma.rn.f32x2 %0, %1, %2, %0;" : "+l"(acc) : "l"(x), "l"(y))

__device__ __forceinline__ float2 up64(ull v) {
    float2 r;
    asm("mov.b64 {%0,%1}, %2;" : "=f"(r.x), "=f"(r.y) : "l"(v));
    return r;
}

// smem layout (floats): A[5200] | B[5200] | W[CHUNK*256]
#define OFF_A 0
#define OFF_B 5200
#define OFF_W 10400
#define SMEM_FLOATS (10400 + CHUNK * 256)
#define SMEM_BYTES  (SMEM_FLOATS * 4)

// ---------------------------------------------------------------- compute ---
__global__ void __launch_bounds__(256, 4)
compute_kernel(const float* __restrict__ F1, const float* __restrict__ F2,
               const float* __restrict__ U1, const float* __restrict__ U2,
               const float* __restrict__ L1, const float* __restrict__ L2)
{
    extern __shared__ float sm[];
    float* sA = sm + OFF_A;   // F1^T [d][20] -> F2 [k][STRD] -> U1 [i][STRD]
    float* sB = sm + OFF_B;   // T [i][STRD]  -> U2 [k][STRD]
    float* sW = sm + OFF_W;   // relu(L) chunk [CHUNK][256]

    const int matId = blockIdx.x;   // 0 -> P (L1), 1 -> Q (L2); Mn split by k
    const int b     = blockIdx.y;
    const int t     = threadIdx.x;

    // 1. F1 transposed: sA[d*20+i] = F1[b,i,d]
    {
        const float* f1 = F1 + (size_t)b * NN * DD;
        #pragma unroll
        for (int idx = t; idx < NN * DD; idx += 256) {
            int i = idx >> 8, d = idx & 255;
            sA[d * NN + i] = f1[idx];
        }
    }
    __syncthreads();

    // 2. T[i,e] = sum_d F1[i,d]*relu(L[d,e]); thread = column e.
    //    Weights staged through smem via coalesced LDG.128 (kills scalar-LDG
    //    LSU bottleneck), relu applied at stage time.
    {
        const int e = t;
        const float* Lsrc = matId ? L2 : L1;
        ull a[10];
        #pragma unroll
        for (int j = 0; j < 10; j++) a[j] = 0ull;

        #pragma unroll 1
        for (int c = 0; c < DD; c += CHUNK) {
            const float4* src = reinterpret_cast<const float4*>(Lsrc + c * DD);
            #pragma unroll
            for (int v = t; v < CHUNK * 64; v += 256) {
                float4 w = src[v];
                w.x = fmaxf(w.x, 0.f); w.y = fmaxf(w.y, 0.f);
                w.z = fmaxf(w.z, 0.f); w.w = fmaxf(w.w, 0.f);
                reinterpret_cast<float4*>(sW)[v] = w;
            }
            __syncthreads();
            #pragma unroll
            for (int j = 0; j < CHUNK; j++) {
                float wr = sW[j * DD + e];            // conflict-free LDS.32
                ull ww;
                asm("mov.b64 %0, {%1,%1};" : "=l"(ww) : "f"(wr));
                const ulonglong2* row =
                    reinterpret_cast<const ulonglong2*>(sA + (c + j) * NN);
                #pragma unroll
                for (int v = 0; v < 5; v++) {         // broadcast LDS.128
                    ulonglong2 fp = row[v];
                    FMA2(a[2 * v],     fp.x, ww);
                    FMA2(a[2 * v + 1], fp.y, ww);
                }
            }
            __syncthreads();
        }
        // store T row-major: sB[i*STRD + e]
        #pragma unroll
        for (int v = 0; v < 10; v++) {
            float2 f = up64(a[v]);
            sB[(2 * v)     * STRD + e] = f.x;
            sB[(2 * v + 1) * STRD + e] = f.y;
        }
    }
    __syncthreads();

    // 3. F2 row-major into sA: sA[k*STRD + d]
    {
        const float4* f2v = reinterpret_cast<const float4*>(F2 + (size_t)b * NN * DD);
        #pragma unroll
        for (int i4 = t; i4 < NN * DD / 4; i4 += 256) {
            int k = i4 >> 6, d4 = i4 & 63;
            *reinterpret_cast<float4*>(sA + k * STRD + d4 * 4) = f2v[i4];
        }
    }
    __syncthreads();

    // 4. P/Q[i,k] = sum_e T[i,e]*F2[k,e] via LDS.128 + f32x2
    {
        float* dst = g_scratch + b * 1200 + matId * 400;
        for (int idx = t; idx < NN * NN; idx += 256) {
            int i = idx / NN, k = idx - i * NN;
            const ulonglong2* Ti = reinterpret_cast<const ulonglong2*>(sB + i * STRD);
            const ulonglong2* Fk = reinterpret_cast<const ulonglong2*>(sA + k * STRD);
            ull a0 = 0, a1 = 0, a2 = 0, a3 = 0;
            #pragma unroll
            for (int v = 0; v < DD / 4; v += 2) {
                ulonglong2 tv0 = Ti[v], tv1 = Ti[v + 1];
                ulonglong2 fv0 = Fk[v], fv1 = Fk[v + 1];
                FMA2(a0, tv0.x, fv0.x);
                FMA2(a1, tv0.y, fv0.y);
                FMA2(a2, tv1.x, fv1.x);
                FMA2(a3, tv1.y, fv1.y);
            }
            float2 s0 = up64(a0), s1 = up64(a1), s2 = up64(a2), s3 = up64(a3);
            dst[idx] = ((s0.x + s0.y) + (s1.x + s1.y)) +
                       ((s2.x + s2.y) + (s3.x + s3.y));
        }
    }
    __syncthreads();

    // 5. U1 -> sA, U2 -> sB, row-major
    {
        const float4* u1v = reinterpret_cast<const float4*>(U1 + (size_t)b * NN * DD);
        const float4* u2v = reinterpret_cast<const float4*>(U2 + (size_t)b * NN * DD);
        #pragma unroll
        for (int i4 = t; i4 < NN * DD / 4; i4 += 256) {
            int k = i4 >> 6, d4 = i4 & 63;
            *reinterpret_cast<float4*>(sA + k * STRD + d4 * 4) = u1v[i4];
            *reinterpret_cast<float4*>(sB + k * STRD + d4 * 4) = u2v[i4];
        }
    }
    __syncthreads();

    // 6. Mn[i,k] = U1[i].U2[k]; each matId block does its k half.
    if (t < 200) {
        int i = t / 10;
        int k = matId * 10 + (t - i * 10);
        const ulonglong2* Ui = reinterpret_cast<const ulonglong2*>(sA + i * STRD);
        const ulonglong2* Uk = reinterpret_cast<const ulonglong2*>(sB + k * STRD);
        ull a0 = 0, a1 = 0, a2 = 0, a3 = 0;
        #pragma unroll
        for (int v = 0; v < DD / 4; v += 2) {
            ulonglong2 tv0 = Ui[v], tv1 = Ui[v + 1];
            ulonglong2 fv0 = Uk[v], fv1 = Uk[v + 1];
            FMA2(a0, tv0.x, fv0.x);
            FMA2(a1, tv0.y, fv0.y);
            FMA2(a2, tv1.x, fv1.x);
            FMA2(a3, tv1.y, fv1.y);
        }
        float2 s0 = up64(a0), s1 = up64(a1), s2 = up64(a2), s3 = up64(a3);
        g_scratch[b * 1200 + 800 + i * NN + k] =
            ((s0.x + s0.y) + (s1.x + s1.y)) + ((s2.x + s2.y) + (s3.x + s3.y));
    }
}

// ------------------------------------------------------------------ write ---
__global__ void __launch_bounds__(512)
write_kernel(float* __restrict__ out)
{
    __shared__ __align__(16) float sPT[NN * 24];   // P^T: [q][y], stride 24
    __shared__ float sQs[NN * 21];                 // Q: [x][q], stride 21
    __shared__ float sPcol[NN];                    // P[x][p]
    __shared__ __align__(16) float sQcol[NN];      // Q[y][p]
    __shared__ float sMn[NN];                      // Mn[x][p]

    const int p = blockIdx.x;
    const int b = blockIdx.y;
    const int t = threadIdx.x;

    const float* Pb = g_scratch + b * 1200;
    const float* Qb = Pb + 400;
    const float* Mb = Pb + 800;

    if (t < 400) {
        int i = t / NN, k = t - i * NN;
        float pv = Pb[t], qv = Qb[t];
        sPT[k * 24 + i] = pv;
        sQs[i * 21 + k] = qv;
        if (k == p) { sPcol[i] = pv; sQcol[i] = qv; }
    }
    if (t >= 480 && t < 500) sMn[t - 480] = Mb[(t - 480) * NN + p];
    __syncthreads();

    if (t < 500) {
        const int x0 = t / 100;
        const int cm = t - x0 * 100;          // float4 index within row
        const int q  = cm / 5;
        const int y0 = (cm - q * 5) * 4;

        float4* ob = reinterpret_cast<float4*>(out) +
                     (size_t)b * 40000 + p * 2000 + cm;

        if (q != p) {
            float4 pt = *reinterpret_cast<const float4*>(sPT + q * 24 + y0);
            float4 qc = *reinterpret_cast<const float4*>(sQcol + y0);
            const float bx = pt.x + qc.x, by = pt.y + qc.y;
            const float bz = pt.z + qc.z, bw = pt.w + qc.w;
            #pragma unroll
            for (int j = 0; j < 4; j++) {
                int x = x0 + 5 * j;
                float c1 = sPcol[x] + sQs[x * 21 + q];
                float4 v = make_float4(c1 + bx, c1 + by, c1 + bz, c1 + bw);
                int dx = x - y0;
                if (dx == 0) v.x = 0.f;
                else if (dx == 1) v.y = 0.f;
                else if (dx == 2) v.z = 0.f;
                else if (dx == 3) v.w = 0.f;
                __stcs(&ob[x * 100], v);      // streaming store: write-once data
            }
        } else {
            #pragma unroll
            for (int j = 0; j < 4; j++) {
                int x = x0 + 5 * j;
                float4 v = make_float4(0.f, 0.f, 0.f, 0.f);
                int dx = x - y0;
                if (dx == 0) v.x = sMn[x];
                else if (dx == 1) v.y = sMn[x];
                else if (dx == 2) v.z = sMn[x];
                else if (dx == 3) v.w = sMn[x];
                __stcs(&ob[x * 100], v);
            }
        }
    }
}

// ----------------------------------------------------------------- launch ---
extern "C" void kernel_launch(void* const* d_in, const int* in_sizes, int n_in,
                              void* d_out, int out_size)
{
    // Inputs: F1,F2,U1,U2,G1,G2,H1,H2,mask,lambda1,lambda2 — pick by size.
    const float* Fs[4] = {nullptr, nullptr, nullptr, nullptr};
    const float* Ls[2] = {nullptr, nullptr};
    int nf = 0, nl = 0;
    for (int i = 0; i < n_in; i++) {
        if (in_sizes[i] == NB * NN * DD) {
            if (nf < 4) Fs[nf++] = (const float*)d_in[i];
        } else if (in_sizes[i] == DD * DD) {
            if (nl < 2) Ls[nl++] = (const float*)d_in[i];
        }
    }

    cudaFuncSetAttribute(compute_kernel,
                         cudaFuncAttributeMaxDynamicSharedMemorySize, SMEM_BYTES);

    compute_kernel<<<dim3(2, NB), 256, SMEM_BYTES>>>(Fs[0], Fs[1], Fs[2], Fs[3],
                                                     Ls[0], Ls[1]);
    write_kernel<<<dim3(NN, NB), 512>>>((float*)d_out);
    (void)out_size;
}

// round 5
// speedup vs baseline: 1.4002x; 1.4002x over previous
#include <cuda_runtime.h>
#include <cstdint>

// out[b, p*20+x, q*20+y] = (x!=y && p!=q) ? P[x,p]+Q[x,q]+Q[y,p]+P[y,q] : 0
//                          + (p==q && x==y) ? Mn[x,p] : 0
// P = F1 @ relu(L1) @ F2^T, Q = F1 @ relu(L2) @ F2^T, Mn = U1 @ U2^T (per batch)
//
// compute_kernel: grid (2 e-halves, 256 batches), 128 threads.
//   Each thread owns ONE column e of L1 AND the same column of L2 -> the
//   A-row broadcast LDS (the round-3/4 bottleneck) is shared between both
//   matrices (A-LDS halved). e-half split -> partial P,Q halves in scratch;
//   write_kernel sums the halves while staging.

#define NB 256
#define NN 20
#define DD 256
#define HK 128          // e-half width
#define STRD 260        // smem row stride for [20][256] tiles
#define TSTR 132        // smem row stride for [20][128] half tiles

typedef unsigned long long ull;

// per batch (stride 2048): P0[400] P1[400] Q0[400] Q1[400] Mn[400]
__device__ float g_scratch[NB * 2048];

#define FMA2(acc, x, y) \
    asm("fma.rn.f32x2 %0, %1, %2, %0;" : "+l"(acc) : "l"(x), "l"(y))

__device__ __forceinline__ float2 up64(ull v) {
    float2 r;
    asm("mov.b64 {%0,%1}, %2;" : "=f"(r.x), "=f"(r.y) : "l"(v));
    return r;
}
__device__ __forceinline__ ull dup(float w) {
    ull r;
    asm("mov.b64 %0, {%1,%1};" : "=l"(r) : "f"(w));
    return r;
}

// smem (floats): sA[5200] | sT1[2640] | sT2[2640] | sF[2640]
#define OFF_A  0
#define OFF_T1 5200
#define OFF_T2 7840
#define OFF_F  10480
#define SMEM_FLOATS 13120
#define SMEM_BYTES  (SMEM_FLOATS * 4)

// ---------------------------------------------------------------- compute ---
__global__ void __launch_bounds__(128, 4)
compute_kernel(const float* __restrict__ F1, const float* __restrict__ F2,
               const float* __restrict__ U1, const float* __restrict__ U2,
               const float* __restrict__ L1, const float* __restrict__ L2)
{
    extern __shared__ float sm[];
    float* sA  = sm + OFF_A;    // F1^T [d][20] (phase2) ; U1 [i][STRD] (phase6)
    float* sT1 = sm + OFF_T1;   // T1 half [i][TSTR]     ; U2 half [r][STRD]
    float* sT2 = sm + OFF_T2;   // T2 half [i][TSTR]
    float* sF  = sm + OFF_F;    // F2 half [k][TSTR]

    const int h = blockIdx.x;   // e-half: e in [h*128, h*128+128)
    const int b = blockIdx.y;
    const int t = threadIdx.x;  // 0..127

    // 1. F1 transposed: sA[d*20+i] = F1[b,i,d]
    {
        const float* f1 = F1 + (size_t)b * NN * DD;
        #pragma unroll
        for (int idx = t; idx < NN * DD; idx += 128) {
            int i = idx >> 8, d = idx & 255;
            sA[d * NN + i] = f1[idx];
        }
    }
    __syncthreads();

    // 2. T1[i,e], T2[i,e] for e = h*128+t; shared A broadcasts.
    {
        const int e = h * HK + t;
        const float* l1p = L1 + e;
        const float* l2p = L2 + e;
        ull a1[10], a2[10];
        #pragma unroll
        for (int j = 0; j < 10; j++) { a1[j] = 0ull; a2[j] = 0ull; }

        float wa1[4], wa2[4], wb1[4], wb2[4];
        #pragma unroll
        for (int j = 0; j < 4; j++) {
            wa1[j] = l1p[j * DD];       wa2[j] = l2p[j * DD];
            wb1[j] = l1p[(4 + j) * DD]; wb2[j] = l2p[(4 + j) * DD];
        }

        #pragma unroll 1
        for (int c = 0; c < DD; c += 8) {
            // compute with buffer A (d = c..c+3)
            #pragma unroll
            for (int j = 0; j < 4; j++) {
                ull ww1 = dup(fmaxf(wa1[j], 0.f));
                ull ww2 = dup(fmaxf(wa2[j], 0.f));
                const ulonglong2* row =
                    reinterpret_cast<const ulonglong2*>(sA + (c + j) * NN);
                #pragma unroll
                for (int v = 0; v < 5; v++) {
                    ulonglong2 fp = row[v];
                    FMA2(a1[2 * v],     fp.x, ww1);
                    FMA2(a1[2 * v + 1], fp.y, ww1);
                    FMA2(a2[2 * v],     fp.x, ww2);
                    FMA2(a2[2 * v + 1], fp.y, ww2);
                }
            }
            if (c + 8 < DD) {
                #pragma unroll
                for (int j = 0; j < 4; j++) {
                    wa1[j] = l1p[(c + 8 + j) * DD];
                    wa2[j] = l2p[(c + 8 + j) * DD];
                }
            }
            // compute with buffer B (d = c+4..c+7)
            #pragma unroll
            for (int j = 0; j < 4; j++) {
                ull ww1 = dup(fmaxf(wb1[j], 0.f));
                ull ww2 = dup(fmaxf(wb2[j], 0.f));
                const ulonglong2* row =
                    reinterpret_cast<const ulonglong2*>(sA + (c + 4 + j) * NN);
                #pragma unroll
                for (int v = 0; v < 5; v++) {
                    ulonglong2 fp = row[v];
                    FMA2(a1[2 * v],     fp.x, ww1);
                    FMA2(a1[2 * v + 1], fp.y, ww1);
                    FMA2(a2[2 * v],     fp.x, ww2);
                    FMA2(a2[2 * v + 1], fp.y, ww2);
                }
            }
            if (c + 12 < DD) {
                #pragma unroll
                for (int j = 0; j < 4; j++) {
                    wb1[j] = l1p[(c + 12 + j) * DD];
                    wb2[j] = l2p[(c + 12 + j) * DD];
                }
            }
        }
        // store half-T row-major: sT[i*TSTR + t]
        #pragma unroll
        for (int v = 0; v < 10; v++) {
            float2 f1v = up64(a1[v]);
            float2 f2v = up64(a2[v]);
            sT1[(2 * v)     * TSTR + t] = f1v.x;
            sT1[(2 * v + 1) * TSTR + t] = f1v.y;
            sT2[(2 * v)     * TSTR + t] = f2v.x;
            sT2[(2 * v + 1) * TSTR + t] = f2v.y;
        }
    }
    __syncthreads();

    // 3. F2 half columns: sF[k*TSTR + j] = F2[b,k,h*128+j]
    {
        const float4* f2v = reinterpret_cast<const float4*>(F2 + (size_t)b * NN * DD);
        #pragma unroll
        for (int i4 = t; i4 < NN * HK / 4; i4 += 128) {
            int k = i4 >> 5, j4 = i4 & 31;
            *reinterpret_cast<float4*>(sF + k * TSTR + j4 * 4) =
                f2v[k * 64 + h * 32 + j4];
        }
    }
    __syncthreads();

    // 4. partial P_h[i,k], Q_h[i,k] over the e-half
    {
        float* dstP = g_scratch + b * 2048 + h * 400;
        float* dstQ = g_scratch + b * 2048 + 800 + h * 400;
        #pragma unroll
        for (int idx = t; idx < NN * NN; idx += 128) {
            int i = idx / NN, k = idx - i * NN;
            const ulonglong2* Ti1 = reinterpret_cast<const ulonglong2*>(sT1 + i * TSTR);
            const ulonglong2* Ti2 = reinterpret_cast<const ulonglong2*>(sT2 + i * TSTR);
            const ulonglong2* Fk  = reinterpret_cast<const ulonglong2*>(sF  + k * TSTR);
            ull p0 = 0, p1 = 0, q0 = 0, q1 = 0;
            #pragma unroll
            for (int v = 0; v < HK / 4; v++) {
                ulonglong2 fv = Fk[v];
                ulonglong2 t1 = Ti1[v];
                ulonglong2 t2 = Ti2[v];
                FMA2(p0, t1.x, fv.x);
                FMA2(p1, t1.y, fv.y);
                FMA2(q0, t2.x, fv.x);
                FMA2(q1, t2.y, fv.y);
            }
            float2 s0 = up64(p0), s1 = up64(p1);
            dstP[idx] = (s0.x + s0.y) + (s1.x + s1.y);
            float2 s2 = up64(q0), s3 = up64(q1);
            dstQ[idx] = (s2.x + s2.y) + (s3.x + s3.y);
        }
    }
    __syncthreads();

    // 5. U1 full -> sA [i][STRD]; U2 rows (h*10..h*10+9) -> sT1 [r][STRD]
    {
        const float4* u1v = reinterpret_cast<const float4*>(U1 + (size_t)b * NN * DD);
        const float4* u2v = reinterpret_cast<const float4*>(U2 + (size_t)b * NN * DD);
        #pragma unroll
        for (int i4 = t; i4 < NN * DD / 4; i4 += 128) {
            int i = i4 >> 6, d4 = i4 & 63;
            *reinterpret_cast<float4*>(sA + i * STRD + d4 * 4) = u1v[i4];
        }
        #pragma unroll
        for (int i4 = t; i4 < 10 * DD / 4; i4 += 128) {
            int r = i4 >> 6, d4 = i4 & 63;
            *reinterpret_cast<float4*>(sT1 + r * STRD + d4 * 4) =
                u2v[(h * 10 + r) * 64 + d4];
        }
    }
    __syncthreads();

    // 6. Mn[i, k=h*10+r] = U1[i].U2[k]
    {
        float* dstM = g_scratch + b * 2048 + 1600;
        #pragma unroll
        for (int idx = t; idx < 200; idx += 128) {
            int i = idx / 10, r = idx - i * 10;
            const ulonglong2* Ui = reinterpret_cast<const ulonglong2*>(sA  + i * STRD);
            const ulonglong2* Uk = reinterpret_cast<const ulonglong2*>(sT1 + r * STRD);
            ull m0 = 0, m1 = 0;
            #pragma unroll
            for (int v = 0; v < DD / 4; v++) {
                ulonglong2 uv = Ui[v];
                ulonglong2 kv = Uk[v];
                FMA2(m0, uv.x, kv.x);
                FMA2(m1, uv.y, kv.y);
            }
            float2 s0 = up64(m0), s1 = up64(m1);
            dstM[i * NN + h * 10 + r] = (s0.x + s0.y) + (s1.x + s1.y);
        }
    }
}

// ------------------------------------------------------------------ write ---
__global__ void __launch_bounds__(512)
write_kernel(float* __restrict__ out)
{
    __shared__ __align__(16) float sPT[NN * 24];   // P^T: [q][y], stride 24
    __shared__ float sQs[NN * 21];                 // Q: [x][q], stride 21
    __shared__ float sPcol[NN];                    // P[x][p]
    __shared__ __align__(16) float sQcol[NN];      // Q[y][p]
    __shared__ float sMn[NN];                      // Mn[x][p]

    const int p = blockIdx.x;
    const int b = blockIdx.y;
    const int t = threadIdx.x;

    const float* s = g_scratch + (size_t)b * 2048;

    if (t < 400) {
        int i = t / NN, k = t - i * NN;
        float pv = s[t]       + s[400 + t];    // P = P0 + P1
        float qv = s[800 + t] + s[1200 + t];   // Q = Q0 + Q1
        sPT[k * 24 + i] = pv;
        sQs[i * 21 + k] = qv;
        if (k == p) { sPcol[i] = pv; sQcol[i] = qv; }
    }
    if (t >= 480 && t < 500) sMn[t - 480] = s[1600 + (t - 480) * NN + p];
    __syncthreads();

    if (t < 500) {
        const int x0 = t / 100;
        const int cm = t - x0 * 100;          // float4 index within row
        const int q  = cm / 5;
        const int y0 = (cm - q * 5) * 4;

        float4* ob = reinterpret_cast<float4*>(out) +
                     (size_t)b * 40000 + p * 2000 + cm;

        if (q != p) {
            float4 pt = *reinterpret_cast<const float4*>(sPT + q * 24 + y0);
            float4 qc = *reinterpret_cast<const float4*>(sQcol + y0);
            const float bx = pt.x + qc.x, by = pt.y + qc.y;
            const float bz = pt.z + qc.z, bw = pt.w + qc.w;
            #pragma unroll
            for (int j = 0; j < 4; j++) {
                int x = x0 + 5 * j;
                float c1 = sPcol[x] + sQs[x * 21 + q];
                float4 v = make_float4(c1 + bx, c1 + by, c1 + bz, c1 + bw);
                int dx = x - y0;
                if (dx == 0) v.x = 0.f;
                else if (dx == 1) v.y = 0.f;
                else if (dx == 2) v.z = 0.f;
                else if (dx == 3) v.w = 0.f;
                __stcs(&ob[x * 100], v);
            }
        } else {
            #pragma unroll
            for (int j = 0; j < 4; j++) {
                int x = x0 + 5 * j;
                float4 v = make_float4(0.f, 0.f, 0.f, 0.f);
                int dx = x - y0;
                if (dx == 0) v.x = sMn[x];
                else if (dx == 1) v.y = sMn[x];
                else if (dx == 2) v.z = sMn[x];
                else if (dx == 3) v.w = sMn[x];
                __stcs(&ob[x * 100], v);
            }
        }
    }
}

// ----------------------------------------------------------------- launch ---
extern "C" void kernel_launch(void* const* d_in, const int* in_sizes, int n_in,
                              void* d_out, int out_size)
{
    // Inputs: F1,F2,U1,U2,G1,G2,H1,H2,mask,lambda1,lambda2 — pick by size.
    const float* Fs[4] = {nullptr, nullptr, nullptr, nullptr};
    const float* Ls[2] = {nullptr, nullptr};
    int nf = 0, nl = 0;
    for (int i = 0; i < n_in; i++) {
        if (in_sizes[i] == NB * NN * DD) {
            if (nf < 4) Fs[nf++] = (const float*)d_in[i];
        } else if (in_sizes[i] == DD * DD) {
            if (nl < 2) Ls[nl++] = (const float*)d_in[i];
        }
    }

    cudaFuncSetAttribute(compute_kernel,
                         cudaFuncAttributeMaxDynamicSharedMemorySize, SMEM_BYTES);

    compute_kernel<<<dim3(2, NB), 128, SMEM_BYTES>>>(Fs[0], Fs[1], Fs[2], Fs[3],
                                                     Ls[0], Ls[1]);
    write_kernel<<<dim3(NN, NB), 512>>>((float*)d_out);
    (void)out_size;
}